// round 5
// baseline (speedup 1.0000x reference)
#include <cuda_runtime.h>
#include <math.h>

#define BB 2
#define SS 2048
#define DD 1024
#define HH 16
#define DH 64
#define MM (BB * SS)   // 4096

// Scratch: [B,H,S,Dh] for q,k,v ; [B,S,D] for attention output
__device__ float g_q[BB * HH * SS * DH];
__device__ float g_k[BB * HH * SS * DH];
__device__ float g_v[BB * HH * SS * DH];
__device__ float g_att[BB * SS * DD];

// ---------------------------------------------------------------------------
// bf16x3 helpers: split a pair of adjacent-k floats into packed bf16x2 hi+mid.
// lo half of the b32 = lower k index (x0).
// ---------------------------------------------------------------------------
__device__ __forceinline__ void split_pair(float x0, float x1, unsigned& hi, unsigned& mid) {
    unsigned h;
    asm("cvt.rn.bf16x2.f32 %0, %1, %2;" : "=r"(h) : "f"(x1), "f"(x0));
    float h0 = __uint_as_float(h << 16);
    float h1 = __uint_as_float(h & 0xFFFF0000u);
    unsigned m;
    asm("cvt.rn.bf16x2.f32 %0, %1, %2;" : "=r"(m) : "f"(x1 - h1), "f"(x0 - h0));
    hi = h; mid = m;
}
__device__ __forceinline__ void split_pair2(float2 v, unsigned& hi, unsigned& mid) {
    split_pair(v.x, v.y, hi, mid);
}

__device__ __forceinline__ void mma_bf16(float& c0, float& c1, float& c2, float& c3,
                                         unsigned a0, unsigned a1, unsigned a2, unsigned a3,
                                         unsigned b0, unsigned b1) {
    asm volatile(
        "mma.sync.aligned.m16n8k16.row.col.f32.bf16.bf16.f32 "
        "{%0,%1,%2,%3}, {%4,%5,%6,%7}, {%8,%9}, {%0,%1,%2,%3};\n"
        : "+f"(c0), "+f"(c1), "+f"(c2), "+f"(c3)
        : "r"(a0), "r"(a1), "r"(a2), "r"(a3), "r"(b0), "r"(b1));
}

// ---------------------------------------------------------------------------
// NT GEMM via bf16x3 tensor cores: C[m,n] = sum_k A[m,k] * W[n,k] (+bias).
// Block tile 128x128, 8 warps, warp tile 32(m)x64(n), k-chunk 32 (2x k16).
// mode 0: fused QKV. A = x, blockIdx.z picks (Wq->g_q, Wk->g_k, Wv->g_v),
//         output in [B,H,S,Dh] layout.
// mode 3: A = g_att, W = W0 (= wo), out -> Cext ([B,S,D]) with bias.
// ---------------------------------------------------------------------------
__global__ void __launch_bounds__(256) gemm_bf16(const float* __restrict__ A,
                                                 const float* __restrict__ W0,
                                                 const float* __restrict__ W1,
                                                 const float* __restrict__ W2,
                                                 const float* __restrict__ bias,
                                                 float* __restrict__ Cext,
                                                 int mode) {
    __shared__ float As[128][36];
    __shared__ float Ws[128][36];

    const int t    = threadIdx.x;
    const int lane = t & 31;
    const int warp = t >> 5;
    const int wm   = warp >> 1;      // 0..3  (m position)
    const int wn   = warp & 1;       // 0..1  (n position)
    const int g    = lane >> 2;      // groupID 0..7
    const int tg   = lane & 3;       // thread in group 0..3

    const int m0 = blockIdx.y * 128;
    const int n0 = blockIdx.x * 128;
    const int z  = blockIdx.z;

    const float* Asrc = (mode == 3) ? g_att : A;
    const float* W = (mode == 3) ? W0 : (z == 0) ? W0 : (z == 1) ? W1 : W2;
    float* C = (mode == 3) ? Cext : (z == 0) ? g_q : (z == 1) ? g_k : g_v;

    float c[2][8][4];
#pragma unroll
    for (int mi = 0; mi < 2; mi++)
#pragma unroll
        for (int ni = 0; ni < 8; ni++)
#pragma unroll
            for (int e = 0; e < 4; e++) c[mi][ni][e] = 0.f;

    for (int k0 = 0; k0 < 1024; k0 += 32) {
        __syncthreads();
#pragma unroll
        for (int i = 0; i < 4; i++) {
            int idx = t + i * 256;
            int row = idx >> 3;
            int fc  = (idx & 7) * 4;
            float4 av = *(const float4*)(Asrc + (size_t)(m0 + row) * 1024 + k0 + fc);
            *(float4*)&As[row][fc] = av;
            float4 wv = *(const float4*)(W + (size_t)(n0 + row) * 1024 + k0 + fc);
            *(float4*)&Ws[row][fc] = wv;
        }
        __syncthreads();

#pragma unroll
        for (int kk = 0; kk < 2; kk++) {
            const int kb = kk * 16;
            unsigned ah[2][4], am[2][4], bh[8][2], bm[8][2];
#pragma unroll
            for (int mi = 0; mi < 2; mi++) {
                const int rb = wm * 32 + mi * 16;
                split_pair2(*(const float2*)&As[rb + g][kb + 2 * tg],         ah[mi][0], am[mi][0]);
                split_pair2(*(const float2*)&As[rb + g + 8][kb + 2 * tg],     ah[mi][1], am[mi][1]);
                split_pair2(*(const float2*)&As[rb + g][kb + 8 + 2 * tg],     ah[mi][2], am[mi][2]);
                split_pair2(*(const float2*)&As[rb + g + 8][kb + 8 + 2 * tg], ah[mi][3], am[mi][3]);
            }
#pragma unroll
            for (int ni = 0; ni < 8; ni++) {
                const int nb = wn * 64 + ni * 8;
                split_pair2(*(const float2*)&Ws[nb + g][kb + 2 * tg],     bh[ni][0], bm[ni][0]);
                split_pair2(*(const float2*)&Ws[nb + g][kb + 8 + 2 * tg], bh[ni][1], bm[ni][1]);
            }
#pragma unroll
            for (int mi = 0; mi < 2; mi++)
#pragma unroll
                for (int ni = 0; ni < 8; ni++) {
                    mma_bf16(c[mi][ni][0], c[mi][ni][1], c[mi][ni][2], c[mi][ni][3],
                             ah[mi][0], ah[mi][1], ah[mi][2], ah[mi][3],
                             bh[ni][0], bh[ni][1]);
                    mma_bf16(c[mi][ni][0], c[mi][ni][1], c[mi][ni][2], c[mi][ni][3],
                             am[mi][0], am[mi][1], am[mi][2], am[mi][3],
                             bh[ni][0], bh[ni][1]);
                    mma_bf16(c[mi][ni][0], c[mi][ni][1], c[mi][ni][2], c[mi][ni][3],
                             ah[mi][0], ah[mi][1], ah[mi][2], ah[mi][3],
                             bm[ni][0], bm[ni][1]);
                }
        }
    }

    // Epilogue: each c fragment element pair (c0,c1)/(c2,c3) is 2 contiguous n.
#pragma unroll
    for (int mi = 0; mi < 2; mi++) {
#pragma unroll
        for (int ni = 0; ni < 8; ni++) {
            int mA = m0 + wm * 32 + mi * 16 + g;
            int mB = mA + 8;
            int n  = n0 + wn * 64 + ni * 8 + 2 * tg;
            if (mode == 3) {
                float bx = bias[n], by = bias[n + 1];
                *(float2*)(C + (size_t)mA * 1024 + n) =
                    make_float2(c[mi][ni][0] + bx, c[mi][ni][1] + by);
                *(float2*)(C + (size_t)mB * 1024 + n) =
                    make_float2(c[mi][ni][2] + bx, c[mi][ni][3] + by);
            } else {
                int h  = n >> 6;
                int dh = n & 63;
                {
                    int b = mA >> 11, s = mA & 2047;
                    *(float2*)(C + (size_t)((b * HH + h) * SS + s) * DH + dh) =
                        make_float2(c[mi][ni][0], c[mi][ni][1]);
                }
                {
                    int b = mB >> 11, s = mB & 2047;
                    *(float2*)(C + (size_t)((b * HH + h) * SS + s) * DH + dh) =
                        make_float2(c[mi][ni][2], c[mi][ni][3]);
                }
            }
        }
    }
}

// ---------------------------------------------------------------------------
// Flash attention via bf16x3 tensor cores.
// Block = 64 query rows, 4 warps (16 rows each), 64-key tiles through SMEM.
// QK^T: 3-term bf16 split. P*V: 3-term bf16 split; P stays thread-local
// (S C-fragment layout == PV A-fragment layout), no SMEM round-trip.
// Reads g_q/g_k/g_v [B,H,S,Dh]; writes g_att [B,S,D].
// ---------------------------------------------------------------------------
__global__ void __launch_bounds__(128) attn_mma() {
    const int b = blockIdx.z;
    const int h = blockIdx.y;
    const int t = threadIdx.x;
    const int warp = t >> 5;
    const int lane = t & 31;
    const int g  = lane >> 2;   // 0..7
    const int tg = lane & 3;    // 0..3
    const int qrow0 = blockIdx.x * 64 + warp * 16;
    const size_t bh = (size_t)(b * HH + h) * SS;

    __shared__ float Ks[64][68];   // fp32 K tile
    __shared__ float Vs[64][68];   // fp32 V tile

    // Q fragments (bf16x2 packed hi+mid) for this warp's 16 rows, pre-scaled.
    unsigned qh[4][4], qm[4][4];
    {
        const float* Q = g_q + (bh + qrow0) * DH;
#pragma unroll
        for (int kb = 0; kb < 4; kb++) {
            float2 a0 = *(const float2*)&Q[g * DH + kb * 16 + 2 * tg];
            float2 a1 = *(const float2*)&Q[(g + 8) * DH + kb * 16 + 2 * tg];
            float2 a2 = *(const float2*)&Q[g * DH + kb * 16 + 8 + 2 * tg];
            float2 a3 = *(const float2*)&Q[(g + 8) * DH + kb * 16 + 8 + 2 * tg];
            split_pair(a0.x * 0.125f, a0.y * 0.125f, qh[kb][0], qm[kb][0]);
            split_pair(a1.x * 0.125f, a1.y * 0.125f, qh[kb][1], qm[kb][1]);
            split_pair(a2.x * 0.125f, a2.y * 0.125f, qh[kb][2], qm[kb][2]);
            split_pair(a3.x * 0.125f, a3.y * 0.125f, qh[kb][3], qm[kb][3]);
        }
    }

    float o[8][4];
#pragma unroll
    for (int ni = 0; ni < 8; ni++)
#pragma unroll
        for (int e = 0; e < 4; e++) o[ni][e] = 0.f;
    float mi0 = -1e30f, mi8 = -1e30f, li0 = 0.f, li8 = 0.f;

    for (int kt = 0; kt < SS; kt += 64) {
        __syncthreads();
#pragma unroll
        for (int i = 0; i < 8; i++) {
            int idx = t + i * 128;
            int r = idx >> 4;
            int c = (idx & 15) * 4;
            *(float4*)&Ks[r][c] = *(const float4*)(g_k + (bh + kt + r) * DH + c);
            *(float4*)&Vs[r][c] = *(const float4*)(g_v + (bh + kt + r) * DH + c);
        }
        __syncthreads();

        // S = Q * K^T (3-term bf16), warp computes 16x64 scores.
        float s[8][4];
#pragma unroll
        for (int ni = 0; ni < 8; ni++)
#pragma unroll
            for (int e = 0; e < 4; e++) s[ni][e] = 0.f;

#pragma unroll
        for (int kb = 0; kb < 4; kb++) {
#pragma unroll
            for (int ni = 0; ni < 8; ni++) {
                float2 k0 = *(const float2*)&Ks[ni * 8 + g][kb * 16 + 2 * tg];
                float2 k1 = *(const float2*)&Ks[ni * 8 + g][kb * 16 + 8 + 2 * tg];
                unsigned bh0, bm0, bh1, bm1;
                split_pair2(k0, bh0, bm0);
                split_pair2(k1, bh1, bm1);
                mma_bf16(s[ni][0], s[ni][1], s[ni][2], s[ni][3],
                         qh[kb][0], qh[kb][1], qh[kb][2], qh[kb][3], bh0, bh1);
                mma_bf16(s[ni][0], s[ni][1], s[ni][2], s[ni][3],
                         qm[kb][0], qm[kb][1], qm[kb][2], qm[kb][3], bh0, bh1);
                mma_bf16(s[ni][0], s[ni][1], s[ni][2], s[ni][3],
                         qh[kb][0], qh[kb][1], qh[kb][2], qh[kb][3], bm0, bm1);
            }
        }

        // Online softmax. Rows: g (elements 0,1) and g+8 (elements 2,3).
        float t0 = mi0, t8 = mi8;
#pragma unroll
        for (int ni = 0; ni < 8; ni++) {
            t0 = fmaxf(t0, fmaxf(s[ni][0], s[ni][1]));
            t8 = fmaxf(t8, fmaxf(s[ni][2], s[ni][3]));
        }
        t0 = fmaxf(t0, __shfl_xor_sync(0xffffffffu, t0, 1));
        t0 = fmaxf(t0, __shfl_xor_sync(0xffffffffu, t0, 2));
        t8 = fmaxf(t8, __shfl_xor_sync(0xffffffffu, t8, 1));
        t8 = fmaxf(t8, __shfl_xor_sync(0xffffffffu, t8, 2));

        float c0 = __expf(mi0 - t0);
        float c8 = __expf(mi8 - t8);
        mi0 = t0; mi8 = t8;
        li0 *= c0; li8 *= c8;

        float rs0 = 0.f, rs8 = 0.f;
#pragma unroll
        for (int ni = 0; ni < 8; ni++) {
            o[ni][0] *= c0; o[ni][1] *= c0;
            o[ni][2] *= c8; o[ni][3] *= c8;
            float p0 = __expf(s[ni][0] - mi0);
            float p1 = __expf(s[ni][1] - mi0);
            float p2 = __expf(s[ni][2] - mi8);
            float p3 = __expf(s[ni][3] - mi8);
            rs0 += p0 + p1;
            rs8 += p2 + p3;
            s[ni][0] = p0; s[ni][1] = p1; s[ni][2] = p2; s[ni][3] = p3;
        }
        li0 += rs0; li8 += rs8;

        // O += P * V (3-term bf16). P is thread-local: the S C-fragment layout
        // is exactly the A-fragment layout for m16n8k16 (k = key index).
#pragma unroll
        for (int kb = 0; kb < 4; kb++) {
            unsigned ah0, ah1, ah2, ah3, am0, am1, am2, am3;
            split_pair(s[2 * kb][0],     s[2 * kb][1],     ah0, am0);
            split_pair(s[2 * kb][2],     s[2 * kb][3],     ah1, am1);
            split_pair(s[2 * kb + 1][0], s[2 * kb + 1][1], ah2, am2);
            split_pair(s[2 * kb + 1][2], s[2 * kb + 1][3], ah3, am3);
#pragma unroll
            for (int ni = 0; ni < 8; ni++) {
                float v00 = Vs[kb * 16 + 2 * tg][ni * 8 + g];
                float v01 = Vs[kb * 16 + 2 * tg + 1][ni * 8 + g];
                float v10 = Vs[kb * 16 + 8 + 2 * tg][ni * 8 + g];
                float v11 = Vs[kb * 16 + 9 + 2 * tg][ni * 8 + g];
                unsigned vh0, vm0, vh1, vm1;
                split_pair(v00, v01, vh0, vm0);
                split_pair(v10, v11, vh1, vm1);
                mma_bf16(o[ni][0], o[ni][1], o[ni][2], o[ni][3],
                         ah0, ah1, ah2, ah3, vh0, vh1);
                mma_bf16(o[ni][0], o[ni][1], o[ni][2], o[ni][3],
                         am0, am1, am2, am3, vh0, vh1);
                mma_bf16(o[ni][0], o[ni][1], o[ni][2], o[ni][3],
                         ah0, ah1, ah2, ah3, vm0, vm1);
            }
        }
    }

    li0 += __shfl_xor_sync(0xffffffffu, li0, 1);
    li0 += __shfl_xor_sync(0xffffffffu, li0, 2);
    li8 += __shfl_xor_sync(0xffffffffu, li8, 1);
    li8 += __shfl_xor_sync(0xffffffffu, li8, 2);
    float inv0 = 1.f / li0;
    float inv8 = 1.f / li8;

    float* O0 = g_att + ((size_t)b * SS + qrow0 + g) * DD + h * DH;
    float* O8 = g_att + ((size_t)b * SS + qrow0 + 8 + g) * DD + h * DH;
#pragma unroll
    for (int ni = 0; ni < 8; ni++) {
        *(float2*)(O0 + ni * 8 + 2 * tg) = make_float2(o[ni][0] * inv0, o[ni][1] * inv0);
        *(float2*)(O8 + ni * 8 + 2 * tg) = make_float2(o[ni][2] * inv8, o[ni][3] * inv8);
    }
}

extern "C" void kernel_launch(void* const* d_in, const int* in_sizes, int n_in,
                              void* d_out, int out_size) {
    const float* x  = (const float*)d_in[0];
    const float* wq = (const float*)d_in[1];
    const float* wk = (const float*)d_in[2];
    const float* wv = (const float*)d_in[3];
    const float* wo = (const float*)d_in[4];
    const float* bo = (const float*)d_in[5];
    float* out = (float*)d_out;

    dim3 gqkv(DD / 128, MM / 128, 3);   // (8, 32, 3) fused Q/K/V projections
    gemm_bf16<<<gqkv, 256>>>(x, wq, wk, wv, nullptr, nullptr, 0);

    dim3 ga(SS / 64, HH, BB);           // (32, 16, 2)
    attn_mma<<<ga, 128>>>();

    dim3 go(DD / 128, MM / 128, 1);
    gemm_bf16<<<go, 256>>>(nullptr, wo, nullptr, nullptr, bo, out, 3);
}